// round 3
// baseline (speedup 1.0000x reference)
#include <cuda_runtime.h>
#include <math.h>

#define BB 256
#define TT 256
#define DD 64
#define HH 256
#define G3 768   // 3*H

// ---------------- device scratch (allocation-free) ----------------
__device__ float g_gi0[2ull * TT * BB * G3];   // 402 MB
__device__ float g_gi1[2ull * TT * BB * G3];   // 402 MB
__device__ float g_y0 [2ull * TT * BB * HH];   // 134 MB
__device__ float g_y1 [2ull * TT * BB * HH];   // 134 MB

// =================================================================
// gi GEMM: gi[dir][t][b][g] = sum_k A[t][b][k] * w_ih[dir][g][k] + b_ih[dir][g]
// MODE 0: A = x[b][t][k]           (KDIM=64)  -> g_gi0
// MODE 1: A = concat(yf0, yb0)[t][b][k] (KDIM=512) -> g_gi1
// Tile 128(m=t*B+b) x 128(g), KC=16, 256 threads, 8x8 per thread.
// =================================================================
template<int KDIM, int MODE>
__global__ __launch_bounds__(256)
void gi_kernel(const float* __restrict__ x,
               const float* __restrict__ w_ih,   // [2][G3][KDIM]
               const float* __restrict__ b_ih)   // [2][G3]
{
    __shared__ float as[16][128];
    __shared__ float bs[16][128];

    const int dir = blockIdx.z;
    const int n0  = blockIdx.x * 128;          // g offset (0..640)
    const int m0  = blockIdx.y * 128;          // m = t*B + b
    const int t   = m0 >> 8;
    const int b0  = m0 & 255;

    const int tid = threadIdx.x;
    const int tm  = tid >> 4;    // 0..15
    const int tn  = tid & 15;    // 0..15

    float acc[8][8];
#pragma unroll
    for (int i = 0; i < 8; i++)
#pragma unroll
        for (int j = 0; j < 8; j++) acc[i][j] = 0.f;

    const float* wdir = w_ih + (size_t)dir * G3 * KDIM;

    for (int kc = 0; kc < KDIM; kc += 16) {
        // ---- load A tile: 128 m x 16 k ----
#pragma unroll
        for (int it = 0; it < 2; it++) {
            int idx = tid + 256 * it;       // 0..511
            int m   = idx >> 2;             // 0..127
            int k4  = (idx & 3) * 4;
            int k   = kc + k4;
            int b   = b0 + m;
            float4 v;
            if (MODE == 0) {
                v = *(const float4*)(x + ((size_t)b * TT + t) * DD + k);
            } else {
                if (k < HH)
                    v = *(const float4*)(g_y0 + ((size_t)t * BB + b) * HH + k);
                else
                    v = *(const float4*)(g_y0 + (size_t)TT * BB * HH +
                                         ((size_t)t * BB + b) * HH + (k - HH));
            }
            as[k4 + 0][m] = v.x; as[k4 + 1][m] = v.y;
            as[k4 + 2][m] = v.z; as[k4 + 3][m] = v.w;
        }
        // ---- load B tile: 128 n x 16 k ----
#pragma unroll
        for (int it = 0; it < 2; it++) {
            int idx = tid + 256 * it;
            int n   = idx >> 2;
            int k4  = (idx & 3) * 4;
            float4 v = *(const float4*)(wdir + (size_t)(n0 + n) * KDIM + kc + k4);
            bs[k4 + 0][n] = v.x; bs[k4 + 1][n] = v.y;
            bs[k4 + 2][n] = v.z; bs[k4 + 3][n] = v.w;
        }
        __syncthreads();

#pragma unroll
        for (int kk = 0; kk < 16; kk++) {
            float a[8], w[8];
            *(float4*)&a[0] = *(const float4*)&as[kk][tm * 8];
            *(float4*)&a[4] = *(const float4*)&as[kk][tm * 8 + 4];
            *(float4*)&w[0] = *(const float4*)&bs[kk][tn * 8];
            *(float4*)&w[4] = *(const float4*)&bs[kk][tn * 8 + 4];
#pragma unroll
            for (int i = 0; i < 8; i++)
#pragma unroll
                for (int j = 0; j < 8; j++)
                    acc[i][j] += a[i] * w[j];
        }
        __syncthreads();
    }

    // ---- epilogue: add bias, store ----
    float bias[8];
    *(float4*)&bias[0] = *(const float4*)&b_ih[dir * G3 + n0 + tn * 8];
    *(float4*)&bias[4] = *(const float4*)&b_ih[dir * G3 + n0 + tn * 8 + 4];

    float* gout = (MODE == 0) ? g_gi0 : g_gi1;
#pragma unroll
    for (int i = 0; i < 8; i++) {
        int b = b0 + tm * 8 + i;
        float* orow = gout + (((size_t)dir * TT + t) * BB + b) * G3 + n0 + tn * 8;
        float4 o0, o1;
        o0.x = acc[i][0] + bias[0]; o0.y = acc[i][1] + bias[1];
        o0.z = acc[i][2] + bias[2]; o0.w = acc[i][3] + bias[3];
        o1.x = acc[i][4] + bias[4]; o1.y = acc[i][5] + bias[5];
        o1.z = acc[i][6] + bias[6]; o1.w = acc[i][7] + bias[7];
        *(float4*)orow       = o0;
        *(float4*)(orow + 4) = o1;
    }
}

// =================================================================
// One recurrent step for both directions of one layer.
// Tile 32 b x 32 j, 3 gate accumulators, 64 threads, 4x4x3 per thread.
// Grid: (8 j-tiles, 8 b-tiles, 2 dirs) = 128 blocks.
// =================================================================
template<int LAYER>
__global__ __launch_bounds__(64)
void step_kernel(const float* __restrict__ w_hh,   // [2][G3][H]
                 const float* __restrict__ b_hh,   // [2][G3]
                 int t)
{
    __shared__ float hs[32][32];       // [k][b]
    __shared__ float ws[3][32][32];    // [gate][k][j]

    const float* gi = (LAYER == 0) ? g_gi0 : g_gi1;
    float*       y  = (LAYER == 0) ? g_y0  : g_y1;

    const int dir  = blockIdx.z;
    const int j0   = blockIdx.x * 32;
    const int b0   = blockIdx.y * 32;
    const int teff = (dir == 0) ? t : (TT - 1 - t);

    const float* gi_t = gi + (((size_t)dir * TT + teff) * BB) * G3;
    float*       y_t  = y  + (((size_t)dir * TT + teff) * BB) * HH;
    const float* h_prev = nullptr;
    if (t > 0) {
        int tprev = (dir == 0) ? (teff - 1) : (teff + 1);
        h_prev = y + (((size_t)dir * TT + tprev) * BB) * HH;
    }
    const float* w  = w_hh + (size_t)dir * G3 * HH;
    const float* bh = b_hh + dir * G3;

    const int tid = threadIdx.x;
    const int tm  = tid >> 3;   // 0..7 -> b group
    const int tn  = tid & 7;    // 0..7 -> j group

    float acc[3][4][4];
#pragma unroll
    for (int g = 0; g < 3; g++)
#pragma unroll
        for (int i = 0; i < 4; i++)
#pragma unroll
            for (int j = 0; j < 4; j++) acc[g][i][j] = 0.f;

    if (h_prev) {
        for (int kc = 0; kc < HH; kc += 32) {
            // fill hs: 32 b x 32 k  (256 float4, 4 per thread)
#pragma unroll
            for (int it = 0; it < 4; it++) {
                int idx = tid + 64 * it;          // 0..255
                int b   = idx & 31;
                int kq  = idx >> 5;               // 0..7
                float4 v = *(const float4*)(h_prev + (size_t)(b0 + b) * HH + kc + kq * 4);
                hs[kq * 4 + 0][b] = v.x; hs[kq * 4 + 1][b] = v.y;
                hs[kq * 4 + 2][b] = v.z; hs[kq * 4 + 3][b] = v.w;
            }
            // fill ws: 3 g x 32 j x 32 k (768 float4, 12 per thread)
#pragma unroll
            for (int it = 0; it < 12; it++) {
                int idx = tid + 64 * it;          // 0..767
                int j   = idx & 31;
                int r   = idx >> 5;               // 0..23
                int kq  = r & 7;
                int g   = r >> 3;
                float4 v = *(const float4*)(w + (size_t)(g * HH + j0 + j) * HH + kc + kq * 4);
                ws[g][kq * 4 + 0][j] = v.x; ws[g][kq * 4 + 1][j] = v.y;
                ws[g][kq * 4 + 2][j] = v.z; ws[g][kq * 4 + 3][j] = v.w;
            }
            __syncthreads();

#pragma unroll
            for (int kk = 0; kk < 32; kk++) {
                float4 hv = *(const float4*)&hs[kk][tm * 4];
                float ha[4] = {hv.x, hv.y, hv.z, hv.w};
#pragma unroll
                for (int g = 0; g < 3; g++) {
                    float4 wv = *(const float4*)&ws[g][kk][tn * 4];
                    float wa[4] = {wv.x, wv.y, wv.z, wv.w};
#pragma unroll
                    for (int i = 0; i < 4; i++)
#pragma unroll
                        for (int j = 0; j < 4; j++)
                            acc[g][i][j] += ha[i] * wa[j];
                }
            }
            __syncthreads();
        }
    }

    // ---- gate math + state update ----
    const int jb = j0 + tn * 4;
    float4 bhr = *(const float4*)&bh[jb];
    float4 bhz = *(const float4*)&bh[HH + jb];
    float4 bhn = *(const float4*)&bh[2 * HH + jb];
    float bhra[4] = {bhr.x, bhr.y, bhr.z, bhr.w};
    float bhza[4] = {bhz.x, bhz.y, bhz.z, bhz.w};
    float bhna[4] = {bhn.x, bhn.y, bhn.z, bhn.w};

#pragma unroll
    for (int i = 0; i < 4; i++) {
        int b = b0 + tm * 4 + i;
        const float* girow = gi_t + (size_t)b * G3;
        float4 gir = *(const float4*)&girow[jb];
        float4 giz = *(const float4*)&girow[HH + jb];
        float4 gin = *(const float4*)&girow[2 * HH + jb];
        float gira[4] = {gir.x, gir.y, gir.z, gir.w};
        float giza[4] = {giz.x, giz.y, giz.z, giz.w};
        float gina[4] = {gin.x, gin.y, gin.z, gin.w};
        float4 hp4;
        if (h_prev) hp4 = *(const float4*)(h_prev + (size_t)b * HH + jb);
        else        hp4 = make_float4(0.f, 0.f, 0.f, 0.f);
        float hpa[4] = {hp4.x, hp4.y, hp4.z, hp4.w};

        float4 ov;
        float outv[4];
#pragma unroll
        for (int j = 0; j < 4; j++) {
            float ghr = acc[0][i][j] + bhra[j];
            float ghz = acc[1][i][j] + bhza[j];
            float ghn = acc[2][i][j] + bhna[j];
            float r = 1.f / (1.f + expf(-(gira[j] + ghr)));
            float z = 1.f / (1.f + expf(-(giza[j] + ghz)));
            float n = tanhf(gina[j] + r * ghn);
            outv[j] = (1.f - z) * n + z * hpa[j];
        }
        ov.x = outv[0]; ov.y = outv[1]; ov.z = outv[2]; ov.w = outv[3];
        *(float4*)(y_t + (size_t)b * HH + jb) = ov;
    }
}

// =================================================================
// Gather: out[b][0:H] = y1_fwd[T-1][b], out[b][H:2H] = y1_bwd[0][b]
// =================================================================
__global__ void gather_kernel(float* __restrict__ out)
{
    int idx = blockIdx.x * blockDim.x + threadIdx.x;   // 0..131071
    int b = idx >> 9;
    int j = idx & 511;
    float v;
    if (j < HH)
        v = g_y1[(((size_t)0 * TT + (TT - 1)) * BB + b) * HH + j];
    else
        v = g_y1[(((size_t)1 * TT + 0) * BB + b) * HH + (j - HH)];
    out[idx] = v;
}

// =================================================================
extern "C" void kernel_launch(void* const* d_in, const int* in_sizes, int n_in,
                              void* d_out, int out_size)
{
    const float* x     = (const float*)d_in[0];
    const float* w_ih0 = (const float*)d_in[1];
    const float* w_hh0 = (const float*)d_in[2];
    const float* b_ih0 = (const float*)d_in[3];
    const float* b_hh0 = (const float*)d_in[4];
    const float* w_ih1 = (const float*)d_in[5];
    const float* w_hh1 = (const float*)d_in[6];
    const float* b_ih1 = (const float*)d_in[7];
    const float* b_hh1 = (const float*)d_in[8];
    float* out = (float*)d_out;

    dim3 gi_grid(6, 512, 2);     // N=768/128, M=65536/128, dirs
    dim3 st_grid(8, 8, 2);       // j-tiles, b-tiles, dirs

    // layer 0 input projection
    gi_kernel<DD, 0><<<gi_grid, 256>>>(x, w_ih0, b_ih0);

    // layer 0 recurrence (both directions per launch)
    for (int t = 0; t < TT; t++)
        step_kernel<0><<<st_grid, 64>>>(w_hh0, b_hh0, t);

    // layer 1 input projection (reads concat(yf0, yb0))
    gi_kernel<2 * HH, 1><<<gi_grid, 256>>>(nullptr, w_ih1, b_ih1);

    // layer 1 recurrence
    for (int t = 0; t < TT; t++)
        step_kernel<1><<<st_grid, 64>>>(w_hh1, b_hh1, t);

    // final output
    gather_kernel<<<512, 256>>>(out);
}

// round 4
// speedup vs baseline: 1.2068x; 1.2068x over previous
#include <cuda_runtime.h>
#include <math.h>

#define BB 256
#define TT 256
#define DD 64
#define HH 256
#define G3 768   // 3*H

// ---------------- device scratch (allocation-free) ----------------
__device__ float g_gi0[2ull * TT * BB * G3];   // 402 MB
__device__ float g_gi1[2ull * TT * BB * G3];   // 402 MB
__device__ float g_y0 [2ull * TT * BB * HH];   // 134 MB
__device__ float g_y1 [2ull * TT * BB * HH];   // 134 MB

// =================================================================
// gi GEMM: gi[dir][t][b][g] = sum_k A[t][b][k] * w_ih[dir][g][k] + b_ih[dir][g]
// MODE 0: A = x[b][t][k]           (KDIM=64)  -> g_gi0
// MODE 1: A = concat(yf0, yb0)[t][b][k] (KDIM=512) -> g_gi1
// Tile 128(m=t*B+b) x 128(g), KC=16, 256 threads, 8x8 per thread.
// =================================================================
template<int KDIM, int MODE>
__global__ __launch_bounds__(256)
void gi_kernel(const float* __restrict__ x,
               const float* __restrict__ w_ih,   // [2][G3][KDIM]
               const float* __restrict__ b_ih)   // [2][G3]
{
    __shared__ float as[16][128];
    __shared__ float bs[16][128];

    const int dir = blockIdx.z;
    const int n0  = blockIdx.x * 128;          // g offset (0..640)
    const int m0  = blockIdx.y * 128;          // m = t*B + b
    const int t   = m0 >> 8;
    const int b0  = m0 & 255;

    const int tid = threadIdx.x;
    const int tm  = tid >> 4;    // 0..15
    const int tn  = tid & 15;    // 0..15

    float acc[8][8];
#pragma unroll
    for (int i = 0; i < 8; i++)
#pragma unroll
        for (int j = 0; j < 8; j++) acc[i][j] = 0.f;

    const float* wdir = w_ih + (size_t)dir * G3 * KDIM;

    for (int kc = 0; kc < KDIM; kc += 16) {
        // ---- load A tile: 128 m x 16 k ----
#pragma unroll
        for (int it = 0; it < 2; it++) {
            int idx = tid + 256 * it;       // 0..511
            int m   = idx >> 2;             // 0..127
            int k4  = (idx & 3) * 4;
            int k   = kc + k4;
            int b   = b0 + m;
            float4 v;
            if (MODE == 0) {
                v = *(const float4*)(x + ((size_t)b * TT + t) * DD + k);
            } else {
                if (k < HH)
                    v = *(const float4*)(g_y0 + ((size_t)t * BB + b) * HH + k);
                else
                    v = *(const float4*)(g_y0 + (size_t)TT * BB * HH +
                                         ((size_t)t * BB + b) * HH + (k - HH));
            }
            as[k4 + 0][m] = v.x; as[k4 + 1][m] = v.y;
            as[k4 + 2][m] = v.z; as[k4 + 3][m] = v.w;
        }
        // ---- load B tile: 128 n x 16 k ----
#pragma unroll
        for (int it = 0; it < 2; it++) {
            int idx = tid + 256 * it;
            int n   = idx >> 2;
            int k4  = (idx & 3) * 4;
            float4 v = *(const float4*)(wdir + (size_t)(n0 + n) * KDIM + kc + k4);
            bs[k4 + 0][n] = v.x; bs[k4 + 1][n] = v.y;
            bs[k4 + 2][n] = v.z; bs[k4 + 3][n] = v.w;
        }
        __syncthreads();

#pragma unroll
        for (int kk = 0; kk < 16; kk++) {
            float a[8], w[8];
            *(float4*)&a[0] = *(const float4*)&as[kk][tm * 8];
            *(float4*)&a[4] = *(const float4*)&as[kk][tm * 8 + 4];
            *(float4*)&w[0] = *(const float4*)&bs[kk][tn * 8];
            *(float4*)&w[4] = *(const float4*)&bs[kk][tn * 8 + 4];
#pragma unroll
            for (int i = 0; i < 8; i++)
#pragma unroll
                for (int j = 0; j < 8; j++)
                    acc[i][j] += a[i] * w[j];
        }
        __syncthreads();
    }

    // ---- epilogue: add bias, store ----
    float bias[8];
    *(float4*)&bias[0] = *(const float4*)&b_ih[dir * G3 + n0 + tn * 8];
    *(float4*)&bias[4] = *(const float4*)&b_ih[dir * G3 + n0 + tn * 8 + 4];

    float* gout = (MODE == 0) ? g_gi0 : g_gi1;
#pragma unroll
    for (int i = 0; i < 8; i++) {
        int b = b0 + tm * 8 + i;
        float* orow = gout + (((size_t)dir * TT + t) * BB + b) * G3 + n0 + tn * 8;
        float4 o0, o1;
        o0.x = acc[i][0] + bias[0]; o0.y = acc[i][1] + bias[1];
        o0.z = acc[i][2] + bias[2]; o0.w = acc[i][3] + bias[3];
        o1.x = acc[i][4] + bias[4]; o1.y = acc[i][5] + bias[5];
        o1.z = acc[i][6] + bias[6]; o1.w = acc[i][7] + bias[7];
        *(float4*)orow       = o0;
        *(float4*)(orow + 4) = o1;
    }
}

// =================================================================
// One recurrent step, both directions of one layer.
// Tile: 16 b x (32 j x 3 gates), 128 threads, 2b x 2j x 3g per thread.
// Grid: (8 j-tiles, 16 b-tiles, 2 dirs) = 256 blocks -> ~2 blocks/SM.
// K-chunk 64 to reduce barrier count.
// =================================================================
template<int LAYER>
__global__ __launch_bounds__(128)
void step_kernel(const float* __restrict__ w_hh,   // [2][G3][H]
                 const float* __restrict__ b_hh,   // [2][G3]
                 int t)
{
    __shared__ float hs[64][16];       // [k][b]
    __shared__ float ws[3][64][32];    // [gate][k][j]

    const float* gi = (LAYER == 0) ? g_gi0 : g_gi1;
    float*       y  = (LAYER == 0) ? g_y0  : g_y1;

    const int dir  = blockIdx.z;
    const int j0   = blockIdx.x * 32;
    const int b0   = blockIdx.y * 16;
    const int teff = (dir == 0) ? t : (TT - 1 - t);

    const float* gi_t = gi + (((size_t)dir * TT + teff) * BB) * G3;
    float*       y_t  = y  + (((size_t)dir * TT + teff) * BB) * HH;
    const float* h_prev = nullptr;
    if (t > 0) {
        int tprev = (dir == 0) ? (teff - 1) : (teff + 1);
        h_prev = y + (((size_t)dir * TT + tprev) * BB) * HH;
    }
    const float* w  = w_hh + (size_t)dir * G3 * HH;
    const float* bh = b_hh + dir * G3;

    const int tid = threadIdx.x;
    const int tm  = tid >> 4;    // 0..7  -> b pair
    const int tn  = tid & 15;    // 0..15 -> j pair
    const int jj  = tn * 2;      // j within tile

    float acc[3][2][2];
#pragma unroll
    for (int g = 0; g < 3; g++)
#pragma unroll
        for (int i = 0; i < 2; i++) { acc[g][i][0] = 0.f; acc[g][i][1] = 0.f; }

    if (h_prev) {
        for (int kc = 0; kc < HH; kc += 64) {
            // ---- fill hs: 16 b x 64 k = 256 float4, 2 per thread ----
#pragma unroll
            for (int it = 0; it < 2; it++) {
                int idx = tid + 128 * it;       // 0..255
                int b   = idx & 15;
                int kq  = idx >> 4;             // 0..15
                float4 v = *(const float4*)(h_prev + (size_t)(b0 + b) * HH + kc + kq * 4);
                hs[kq * 4 + 0][b] = v.x; hs[kq * 4 + 1][b] = v.y;
                hs[kq * 4 + 2][b] = v.z; hs[kq * 4 + 3][b] = v.w;
            }
            // ---- fill ws: 3 g x 32 j x 64 k = 1536 float4, 12 per thread ----
#pragma unroll
            for (int it = 0; it < 12; it++) {
                int idx = tid + 128 * it;       // 0..1535
                int j   = idx & 31;
                int r   = idx >> 5;             // 0..47
                int kq  = r & 15;               // 0..15
                int g   = r >> 4;               // 0..2
                float4 v = *(const float4*)(w + (size_t)(g * HH + j0 + j) * HH + kc + kq * 4);
                ws[g][kq * 4 + 0][j] = v.x; ws[g][kq * 4 + 1][j] = v.y;
                ws[g][kq * 4 + 2][j] = v.z; ws[g][kq * 4 + 3][j] = v.w;
            }
            __syncthreads();

#pragma unroll
            for (int kk = 0; kk < 64; kk++) {
                float2 hv = *(const float2*)&hs[kk][tm * 2];
#pragma unroll
                for (int g = 0; g < 3; g++) {
                    float2 wv = *(const float2*)&ws[g][kk][jj];
                    acc[g][0][0] += hv.x * wv.x; acc[g][0][1] += hv.x * wv.y;
                    acc[g][1][0] += hv.y * wv.x; acc[g][1][1] += hv.y * wv.y;
                }
            }
            __syncthreads();
        }
    }

    // ---- gate math + state update ----
    const int jg = j0 + jj;
    float2 bhr = *(const float2*)&bh[jg];
    float2 bhz = *(const float2*)&bh[HH + jg];
    float2 bhn = *(const float2*)&bh[2 * HH + jg];

#pragma unroll
    for (int i = 0; i < 2; i++) {
        int b = b0 + tm * 2 + i;
        const float* girow = gi_t + (size_t)b * G3;
        float2 gir = *(const float2*)&girow[jg];
        float2 giz = *(const float2*)&girow[HH + jg];
        float2 gin = *(const float2*)&girow[2 * HH + jg];
        float2 hp = make_float2(0.f, 0.f);
        if (h_prev) hp = *(const float2*)(h_prev + (size_t)b * HH + jg);

        float r0 = 1.f / (1.f + expf(-(gir.x + acc[0][i][0] + bhr.x)));
        float r1 = 1.f / (1.f + expf(-(gir.y + acc[0][i][1] + bhr.y)));
        float z0 = 1.f / (1.f + expf(-(giz.x + acc[1][i][0] + bhz.x)));
        float z1 = 1.f / (1.f + expf(-(giz.y + acc[1][i][1] + bhz.y)));
        float n0 = tanhf(gin.x + r0 * (acc[2][i][0] + bhn.x));
        float n1 = tanhf(gin.y + r1 * (acc[2][i][1] + bhn.y));

        float2 o;
        o.x = (1.f - z0) * n0 + z0 * hp.x;
        o.y = (1.f - z1) * n1 + z1 * hp.y;
        *(float2*)(y_t + (size_t)b * HH + jg) = o;
    }
}

// =================================================================
// Gather: out[b][0:H] = y1_fwd[T-1][b], out[b][H:2H] = y1_bwd[0][b]
// =================================================================
__global__ void gather_kernel(float* __restrict__ out)
{
    int idx = blockIdx.x * blockDim.x + threadIdx.x;   // 0..131071
    int b = idx >> 9;
    int j = idx & 511;
    float v;
    if (j < HH)
        v = g_y1[(((size_t)0 * TT + (TT - 1)) * BB + b) * HH + j];
    else
        v = g_y1[(((size_t)1 * TT + 0) * BB + b) * HH + (j - HH)];
    out[idx] = v;
}

// =================================================================
extern "C" void kernel_launch(void* const* d_in, const int* in_sizes, int n_in,
                              void* d_out, int out_size)
{
    const float* x     = (const float*)d_in[0];
    const float* w_ih0 = (const float*)d_in[1];
    const float* w_hh0 = (const float*)d_in[2];
    const float* b_ih0 = (const float*)d_in[3];
    const float* b_hh0 = (const float*)d_in[4];
    const float* w_ih1 = (const float*)d_in[5];
    const float* w_hh1 = (const float*)d_in[6];
    const float* b_ih1 = (const float*)d_in[7];
    const float* b_hh1 = (const float*)d_in[8];
    float* out = (float*)d_out;

    dim3 gi_grid(6, 512, 2);     // N=768/128, M=65536/128, dirs
    dim3 st_grid(8, 16, 2);      // j-tiles, b-tiles, dirs = 256 blocks

    // layer 0 input projection
    gi_kernel<DD, 0><<<gi_grid, 256>>>(x, w_ih0, b_ih0);

    // layer 0 recurrence (both directions per launch)
    for (int t = 0; t < TT; t++)
        step_kernel<0><<<st_grid, 128>>>(w_hh0, b_hh0, t);

    // layer 1 input projection (reads concat(yf0, yb0))
    gi_kernel<2 * HH, 1><<<gi_grid, 256>>>(nullptr, w_ih1, b_ih1);

    // layer 1 recurrence
    for (int t = 0; t < TT; t++)
        step_kernel<1><<<st_grid, 128>>>(w_hh1, b_hh1, t);

    // final output
    gather_kernel<<<512, 256>>>(out);
}

// round 5
// speedup vs baseline: 1.9307x; 1.5998x over previous
#include <cuda_runtime.h>
#include <math.h>

#define BB 256
#define TT 256
#define DD 64
#define HH 256
#define G3 768   // 3*H
#define NBLK 128

// ---------------- device scratch (allocation-free) ----------------
__device__ float g_gi0[2ull * TT * BB * G3];
__device__ float g_gi1[2ull * TT * BB * G3];
__device__ float g_y0 [2ull * TT * BB * HH];
__device__ float g_y1 [2ull * TT * BB * HH];
__device__ unsigned g_ctr1;   // step barrier counter (zero-init)
__device__ unsigned g_ctr2;   // exit counter (zero-init)

// =================================================================
// gi GEMM (unchanged): gi[dir][t][b][g] = A @ w_ih^T + b_ih
// =================================================================
template<int KDIM, int MODE>
__global__ __launch_bounds__(256)
void gi_kernel(const float* __restrict__ x,
               const float* __restrict__ w_ih,
               const float* __restrict__ b_ih)
{
    __shared__ float as[16][128];
    __shared__ float bs[16][128];

    const int dir = blockIdx.z;
    const int n0  = blockIdx.x * 128;
    const int m0  = blockIdx.y * 128;
    const int t   = m0 >> 8;
    const int b0  = m0 & 255;

    const int tid = threadIdx.x;
    const int tm  = tid >> 4;
    const int tn  = tid & 15;

    float acc[8][8];
#pragma unroll
    for (int i = 0; i < 8; i++)
#pragma unroll
        for (int j = 0; j < 8; j++) acc[i][j] = 0.f;

    const float* wdir = w_ih + (size_t)dir * G3 * KDIM;

    for (int kc = 0; kc < KDIM; kc += 16) {
#pragma unroll
        for (int it = 0; it < 2; it++) {
            int idx = tid + 256 * it;
            int m   = idx >> 2;
            int k4  = (idx & 3) * 4;
            int k   = kc + k4;
            int b   = b0 + m;
            float4 v;
            if (MODE == 0) {
                v = *(const float4*)(x + ((size_t)b * TT + t) * DD + k);
            } else {
                if (k < HH)
                    v = *(const float4*)(g_y0 + ((size_t)t * BB + b) * HH + k);
                else
                    v = *(const float4*)(g_y0 + (size_t)TT * BB * HH +
                                         ((size_t)t * BB + b) * HH + (k - HH));
            }
            as[k4 + 0][m] = v.x; as[k4 + 1][m] = v.y;
            as[k4 + 2][m] = v.z; as[k4 + 3][m] = v.w;
        }
#pragma unroll
        for (int it = 0; it < 2; it++) {
            int idx = tid + 256 * it;
            int n   = idx >> 2;
            int k4  = (idx & 3) * 4;
            float4 v = *(const float4*)(wdir + (size_t)(n0 + n) * KDIM + kc + k4);
            bs[k4 + 0][n] = v.x; bs[k4 + 1][n] = v.y;
            bs[k4 + 2][n] = v.z; bs[k4 + 3][n] = v.w;
        }
        __syncthreads();

#pragma unroll
        for (int kk = 0; kk < 16; kk++) {
            float a[8], w[8];
            *(float4*)&a[0] = *(const float4*)&as[kk][tm * 8];
            *(float4*)&a[4] = *(const float4*)&as[kk][tm * 8 + 4];
            *(float4*)&w[0] = *(const float4*)&bs[kk][tn * 8];
            *(float4*)&w[4] = *(const float4*)&bs[kk][tn * 8 + 4];
#pragma unroll
            for (int i = 0; i < 8; i++)
#pragma unroll
                for (int j = 0; j < 8; j++)
                    acc[i][j] += a[i] * w[j];
        }
        __syncthreads();
    }

    float bias[8];
    *(float4*)&bias[0] = *(const float4*)&b_ih[dir * G3 + n0 + tn * 8];
    *(float4*)&bias[4] = *(const float4*)&b_ih[dir * G3 + n0 + tn * 8 + 4];

    float* gout = (MODE == 0) ? g_gi0 : g_gi1;
#pragma unroll
    for (int i = 0; i < 8; i++) {
        int b = b0 + tm * 8 + i;
        float* orow = gout + (((size_t)dir * TT + t) * BB + b) * G3 + n0 + tn * 8;
        float4 o0, o1;
        o0.x = acc[i][0] + bias[0]; o0.y = acc[i][1] + bias[1];
        o0.z = acc[i][2] + bias[2]; o0.w = acc[i][3] + bias[3];
        o1.x = acc[i][4] + bias[4]; o1.y = acc[i][5] + bias[5];
        o1.z = acc[i][6] + bias[6]; o1.w = acc[i][7] + bias[7];
        *(float4*)orow       = o0;
        *(float4*)(orow + 4) = o1;
    }
}

// =================================================================
// Persistent per-layer recurrence kernel.
// Grid = 128 blocks (2 dirs x 4 b-tiles(64) x 16 j-tiles(16)), 256 thr.
// Weights cached in smem for all 256 steps; global spin barrier per step.
// smem: ws[3][256][16] (48KB) + hs[64][260] padded (65KB) = ~113KB dynamic.
// =================================================================
#define HS_PITCH 260   // 256 + 4 pad: float4-aligned, banks shift by 4 per row

template<int LAYER>
__global__ __launch_bounds__(256)
void layer_kernel(const float* __restrict__ w_hh,   // [2][G3][H]
                  const float* __restrict__ b_hh)   // [2][G3]
{
    extern __shared__ float sm[];
    float* ws = sm;                    // [g][k][j16]: 3*256*16
    float* hs = sm + 3 * 256 * 16;     // [b64][HS_PITCH]

    const int bid = blockIdx.x;
    const int dir = bid >> 6;
    const int rr  = bid & 63;
    const int j0  = (rr & 15) * 16;
    const int b0  = (rr >> 4) * 64;

    const int tid = threadIdx.x;
    const int tn  = tid & 15;          // j column within tile
    const int tm  = tid >> 4;          // 0..15 -> b group of 4
    const int bb  = tm * 4;            // local b base
    const int jg  = j0 + tn;           // global j (0..255)

    const float* gi = LAYER ? g_gi1 : g_gi0;
    float*       y  = LAYER ? g_y1  : g_y0;
    const float* w  = w_hh + (size_t)dir * G3 * HH;
    const float* bh = b_hh + dir * G3;

    // ---- load weight slice once: ws[g][k][j] = w[(g*H + j0+j)][k] ----
#pragma unroll
    for (int it = 0; it < 12; it++) {
        int idx = tid + 256 * it;          // 0..3071 = g*1024 + kq*16 + j
        int j   = idx & 15;
        int kq  = (idx >> 4) & 63;
        int g   = idx >> 10;
        float4 v = *(const float4*)(w + (size_t)(g * HH + j0 + j) * HH + kq * 4);
        ws[(g * 256 + kq * 4 + 0) * 16 + j] = v.x;
        ws[(g * 256 + kq * 4 + 1) * 16 + j] = v.y;
        ws[(g * 256 + kq * 4 + 2) * 16 + j] = v.z;
        ws[(g * 256 + kq * 4 + 3) * 16 + j] = v.w;
    }

    // per-thread constants (fixed across steps)
    const float bhr = bh[jg];
    const float bhz = bh[HH + jg];
    const float bhn = bh[2 * HH + jg];

    __syncthreads();

    volatile unsigned* vc1 = &g_ctr1;

    for (int t = 0; t < TT; t++) {
        const int teff = (dir == 0) ? t : (TT - 1 - t);
        const float* gi_t = gi + ((size_t)(dir * TT + teff) * BB) * G3;
        float*       y_t  = y  + ((size_t)(dir * TT + teff) * BB) * HH;

        // ---- prefetch gi into registers (hides DRAM latency under k-loop) ----
        float gr[4], gz[4], gn[4];
#pragma unroll
        for (int i = 0; i < 4; i++) {
            const float* row = gi_t + (size_t)(b0 + bb + i) * G3;
            gr[i] = row[jg];
            gz[i] = row[HH + jg];
            gn[i] = row[2 * HH + jg];
        }

        float accr[4] = {0.f, 0.f, 0.f, 0.f};
        float accz[4] = {0.f, 0.f, 0.f, 0.f};
        float accn[4] = {0.f, 0.f, 0.f, 0.f};
        float hp[4]   = {0.f, 0.f, 0.f, 0.f};

        if (t > 0) {
            const int tprev = (dir == 0) ? (teff - 1) : (teff + 1);
            const float* h_prev = y + ((size_t)(dir * TT + tprev) * BB) * HH;

            // ---- stage h slice: hs[b][k], coalesced float4 ----
#pragma unroll
            for (int it = 0; it < 16; it++) {
                int idx = tid + 256 * it;      // 0..4095
                int kq  = idx & 63;
                int b   = idx >> 6;
                float4 v = *(const float4*)(h_prev + (size_t)(b0 + b) * HH + kq * 4);
                *(float4*)&hs[b * HS_PITCH + kq * 4] = v;
            }
            __syncthreads();

            // ---- GEMM: 4b x 16j(tile) x 3 gates per thread over K=256 ----
#pragma unroll 4
            for (int k = 0; k < HH; k++) {
                float wr = ws[(0 * 256 + k) * 16 + tn];
                float wz = ws[(1 * 256 + k) * 16 + tn];
                float wn = ws[(2 * 256 + k) * 16 + tn];
#pragma unroll
                for (int i = 0; i < 4; i++) {
                    float h = hs[(bb + i) * HS_PITCH + k];
                    accr[i] += h * wr;
                    accz[i] += h * wz;
                    accn[i] += h * wn;
                }
            }

#pragma unroll
            for (int i = 0; i < 4; i++)
                hp[i] = hs[(bb + i) * HS_PITCH + jg];
        }

        // ---- gate math + write ----
#pragma unroll
        for (int i = 0; i < 4; i++) {
            float r = 1.f / (1.f + expf(-(gr[i] + accr[i] + bhr)));
            float z = 1.f / (1.f + expf(-(gz[i] + accz[i] + bhz)));
            float n = tanhf(gn[i] + r * (accn[i] + bhn));
            float o = (1.f - z) * n + z * hp[i];
            y_t[(size_t)(b0 + bb + i) * HH + jg] = o;
        }

        // ---- grid barrier (skip after final step) ----
        if (t < TT - 1) {
            __syncthreads();                 // all threads done reading hs / writing y
            if (tid == 0) {
                __threadfence();             // publish y_t
                atomicAdd(&g_ctr1, 1);
                unsigned target = (unsigned)(t + 1) * NBLK;
                while (*vc1 < target) { }
                __threadfence();             // invalidate L1 before reading peer h
            }
            __syncthreads();
        }
    }

    // ---- deadlock-safe counter reset for next launch / graph replay ----
    __syncthreads();
    if (tid == 0) {
        atomicAdd(&g_ctr2, 1);
        if (bid == 0) {
            volatile unsigned* vc2 = &g_ctr2;
            while (*vc2 < NBLK) { }
            *(volatile unsigned*)&g_ctr1 = 0;
            *(volatile unsigned*)&g_ctr2 = 0;
            __threadfence();
        }
    }
}

// =================================================================
// Gather: out[b][0:H] = y1_fwd[T-1][b], out[b][H:2H] = y1_bwd[0][b]
// =================================================================
__global__ void gather_kernel(float* __restrict__ out)
{
    int idx = blockIdx.x * blockDim.x + threadIdx.x;
    int b = idx >> 9;
    int j = idx & 511;
    float v;
    if (j < HH)
        v = g_y1[(((size_t)0 * TT + (TT - 1)) * BB + b) * HH + j];
    else
        v = g_y1[(((size_t)1 * TT + 0) * BB + b) * HH + (j - HH)];
    out[idx] = v;
}

// =================================================================
extern "C" void kernel_launch(void* const* d_in, const int* in_sizes, int n_in,
                              void* d_out, int out_size)
{
    const float* x     = (const float*)d_in[0];
    const float* w_ih0 = (const float*)d_in[1];
    const float* w_hh0 = (const float*)d_in[2];
    const float* b_ih0 = (const float*)d_in[3];
    const float* b_hh0 = (const float*)d_in[4];
    const float* w_ih1 = (const float*)d_in[5];
    const float* w_hh1 = (const float*)d_in[6];
    const float* b_ih1 = (const float*)d_in[7];
    const float* b_hh1 = (const float*)d_in[8];
    float* out = (float*)d_out;

    const int smem_bytes = (3 * 256 * 16 + 64 * HS_PITCH) * sizeof(float);
    cudaFuncSetAttribute(layer_kernel<0>,
                         cudaFuncAttributeMaxDynamicSharedMemorySize, smem_bytes);
    cudaFuncSetAttribute(layer_kernel<1>,
                         cudaFuncAttributeMaxDynamicSharedMemorySize, smem_bytes);

    dim3 gi_grid(6, 512, 2);

    gi_kernel<DD, 0><<<gi_grid, 256>>>(x, w_ih0, b_ih0);
    layer_kernel<0><<<NBLK, 256, smem_bytes>>>(w_hh0, b_hh0);
    gi_kernel<2 * HH, 1><<<gi_grid, 256>>>(nullptr, w_ih1, b_ih1);
    layer_kernel<1><<<NBLK, 256, smem_bytes>>>(w_hh1, b_hh1);
    gather_kernel<<<512, 256>>>(out);
}

// round 7
// speedup vs baseline: 2.3296x; 1.2066x over previous
#include <cuda_runtime.h>
#include <math.h>
#include <cstdint>

#define BB 256
#define TT 256
#define DD 64
#define HH 256
#define G3 768   // 3*H
#define NBLK 128

// ---------------- device scratch (allocation-free) ----------------
__device__ float g_gi0[2ull * TT * BB * G3];
__device__ float g_gi1[2ull * TT * BB * G3];
__device__ float g_y0 [2ull * TT * BB * HH];
__device__ float g_y1 [2ull * TT * BB * HH];
__device__ unsigned g_ctrs[8];   // per-group step counters (zero-init)
__device__ unsigned g_ctre[8];   // per-group exit counters (zero-init)

// ================= mma.sync tf32 helpers (sm_80+, family-agnostic) ========
__device__ __forceinline__ uint32_t f2tf32(float f) {
    uint32_t r;
    asm("cvt.rna.tf32.f32 %0, %1;" : "=r"(r) : "f"(f));
    return r;
}
__device__ __forceinline__ void mma1688(float* d, const uint32_t* a, const uint32_t* b) {
    asm volatile(
        "mma.sync.aligned.m16n8k8.row.col.f32.tf32.tf32.f32 "
        "{%0,%1,%2,%3}, {%4,%5,%6,%7}, {%8,%9}, {%0,%1,%2,%3};"
        : "+f"(d[0]), "+f"(d[1]), "+f"(d[2]), "+f"(d[3])
        : "r"(a[0]), "r"(a[1]), "r"(a[2]), "r"(a[3]), "r"(b[0]), "r"(b[1]));
}

// =================================================================
// gi GEMM via mma.sync tf32.
// C[m=t*B+b][n=gate] = A[m][k] * W[n][k]^T + bias[n]
// Block: 256 thr = 8 warps (4 m x 2 n), tile M=128, N=64, KC=32.
// Warp tile 32x32 = 2 m-frags(16) x 4 n-frags(8).
// MODE 0: A = x[b][t][k] (KDIM=64)  -> g_gi0
// MODE 1: A = concat(yf0,yb0)[t][b][k] (KDIM=512) -> g_gi1
// =================================================================
#define KC 32
#define AP 36   // smem pitch (floats): (4*row + col) banks, conflict-free frags

template<int KDIM, int MODE>
__global__ __launch_bounds__(256)
void gi_mma_kernel(const float* __restrict__ x,
                   const float* __restrict__ w_ih,   // [2][G3][KDIM]
                   const float* __restrict__ b_ih)   // [2][G3]
{
    __shared__ uint32_t as[128 * AP];   // A tile (tf32 bits)
    __shared__ uint32_t wsm[64 * AP];   // W tile (tf32 bits)

    const int tid  = threadIdx.x;
    const int wid  = tid >> 5;
    const int lane = tid & 31;
    const int g    = lane >> 2;     // 0..7
    const int tig  = lane & 3;      // 0..3

    const int bx  = blockIdx.x;     // 0..511
    const int t   = bx >> 1;
    const int b0  = (bx & 1) * 128;
    const int n0  = blockIdx.y * 64;
    const int dir = blockIdx.z;

    const int wm = wid >> 1;        // 0..3 (m sub-tile of 32)
    const int wn = wid & 1;         // 0..1 (n sub-tile of 32)

    const float* wdir = w_ih + (size_t)dir * G3 * KDIM;

    float acc[2][4][4];
#pragma unroll
    for (int mf = 0; mf < 2; mf++)
#pragma unroll
        for (int nf = 0; nf < 4; nf++)
#pragma unroll
            for (int q = 0; q < 4; q++) acc[mf][nf][q] = 0.f;

    for (int c = 0; c < KDIM / KC; c++) {
        const int koff = c * KC;

        // ---- stage A: 128 rows x 32 k (4 float4 per thread) ----
#pragma unroll
        for (int i = 0; i < 4; i++) {
            int idx = tid + 256 * i;     // 0..1023
            int row = idx >> 3;
            int kq  = (idx & 7) * 4;
            float4 v;
            if (MODE == 0) {
                v = *(const float4*)(x + ((size_t)(b0 + row) * TT + t) * DD + koff + kq);
            } else {
                int k = koff + kq;
                if (k < HH)
                    v = *(const float4*)(g_y0 + ((size_t)t * BB + b0 + row) * HH + k);
                else
                    v = *(const float4*)(g_y0 + (size_t)TT * BB * HH +
                                         ((size_t)t * BB + b0 + row) * HH + (k - HH));
            }
            uint32_t* p = &as[row * AP + kq];
            p[0] = f2tf32(v.x); p[1] = f2tf32(v.y);
            p[2] = f2tf32(v.z); p[3] = f2tf32(v.w);
        }
        // ---- stage W: 64 rows x 32 k (2 float4 per thread) ----
#pragma unroll
        for (int i = 0; i < 2; i++) {
            int idx = tid + 256 * i;     // 0..511
            int row = idx >> 3;
            int kq  = (idx & 7) * 4;
            float4 v = *(const float4*)(wdir + (size_t)(n0 + row) * KDIM + koff + kq);
            uint32_t* p = &wsm[row * AP + kq];
            p[0] = f2tf32(v.x); p[1] = f2tf32(v.y);
            p[2] = f2tf32(v.z); p[3] = f2tf32(v.w);
        }
        __syncthreads();

#pragma unroll
        for (int kk = 0; kk < KC; kk += 8) {
            uint32_t afr[2][4], bfr[4][2];
#pragma unroll
            for (int mf = 0; mf < 2; mf++) {
                int base = wm * 32 + mf * 16;
                afr[mf][0] = as[(base + g)     * AP + kk + tig];
                afr[mf][1] = as[(base + g + 8) * AP + kk + tig];
                afr[mf][2] = as[(base + g)     * AP + kk + tig + 4];
                afr[mf][3] = as[(base + g + 8) * AP + kk + tig + 4];
            }
#pragma unroll
            for (int nf = 0; nf < 4; nf++) {
                int nb = wn * 32 + nf * 8;
                bfr[nf][0] = wsm[(nb + g) * AP + kk + tig];
                bfr[nf][1] = wsm[(nb + g) * AP + kk + tig + 4];
            }
#pragma unroll
            for (int mf = 0; mf < 2; mf++)
#pragma unroll
                for (int nf = 0; nf < 4; nf++)
                    mma1688(acc[mf][nf], afr[mf], bfr[nf]);
        }
        __syncthreads();
    }

    // ---- epilogue: bias + store (float2 per c-pair) ----
    float* gout = (MODE == 0) ? g_gi0 : g_gi1;
    const float* bias = b_ih + dir * G3;

#pragma unroll
    for (int mf = 0; mf < 2; mf++) {
#pragma unroll
        for (int rs = 0; rs < 2; rs++) {
            int mloc = wm * 32 + mf * 16 + g + rs * 8;
            int b = b0 + mloc;
            float* orow = gout + (((size_t)dir * TT + t) * BB + b) * G3 + n0;
#pragma unroll
            for (int nf = 0; nf < 4; nf++) {
                int col = wn * 32 + nf * 8 + 2 * tig;
                float2 o;
                o.x = acc[mf][nf][rs * 2 + 0] + bias[n0 + col];
                o.y = acc[mf][nf][rs * 2 + 1] + bias[n0 + col + 1];
                *(float2*)(orow + col) = o;
            }
        }
    }
}

// =================================================================
// Persistent per-layer recurrence kernel (fp32, weights in smem).
// Grid = 128 blocks (dir | b-tile(64) | j-tile(16)), 256 threads.
// Barrier: 8 independent groups of 16 blocks sharing (dir, b-tile).
// =================================================================
#define HS_PITCH 260

template<int LAYER>
__global__ __launch_bounds__(256)
void layer_kernel(const float* __restrict__ w_hh,   // [2][G3][H]
                  const float* __restrict__ b_hh)   // [2][G3]
{
    extern __shared__ float sm[];
    float* ws = sm;                    // [g][k][j16]
    float* hs = sm + 3 * 256 * 16;     // [b64][HS_PITCH]

    const int bid = blockIdx.x;
    const int dir = bid >> 6;
    const int rr  = bid & 63;
    const int j0  = (rr & 15) * 16;
    const int b0  = (rr >> 4) * 64;
    const int grp = bid >> 4;          // (dir, b-tile) group of 16 blocks

    const int tid = threadIdx.x;
    const int tn  = tid & 15;
    const int tm  = tid >> 4;
    const int bb  = tm * 4;
    const int jg  = j0 + tn;

    const float* gi = LAYER ? g_gi1 : g_gi0;
    float*       y  = LAYER ? g_y1  : g_y0;
    const float* w  = w_hh + (size_t)dir * G3 * HH;
    const float* bh = b_hh + dir * G3;

#pragma unroll
    for (int it = 0; it < 12; it++) {
        int idx = tid + 256 * it;
        int j   = idx & 15;
        int kq  = (idx >> 4) & 63;
        int g   = idx >> 10;
        float4 v = *(const float4*)(w + (size_t)(g * HH + j0 + j) * HH + kq * 4);
        ws[(g * 256 + kq * 4 + 0) * 16 + j] = v.x;
        ws[(g * 256 + kq * 4 + 1) * 16 + j] = v.y;
        ws[(g * 256 + kq * 4 + 2) * 16 + j] = v.z;
        ws[(g * 256 + kq * 4 + 3) * 16 + j] = v.w;
    }

    const float bhr = bh[jg];
    const float bhz = bh[HH + jg];
    const float bhn = bh[2 * HH + jg];

    __syncthreads();

    volatile unsigned* vc = &g_ctrs[grp];

    for (int t = 0; t < TT; t++) {
        const int teff = (dir == 0) ? t : (TT - 1 - t);
        const float* gi_t = gi + ((size_t)(dir * TT + teff) * BB) * G3;
        float*       y_t  = y  + ((size_t)(dir * TT + teff) * BB) * HH;

        float gr[4], gz[4], gn[4];
#pragma unroll
        for (int i = 0; i < 4; i++) {
            const float* row = gi_t + (size_t)(b0 + bb + i) * G3;
            gr[i] = row[jg];
            gz[i] = row[HH + jg];
            gn[i] = row[2 * HH + jg];
        }

        float accr[4] = {0.f, 0.f, 0.f, 0.f};
        float accz[4] = {0.f, 0.f, 0.f, 0.f};
        float accn[4] = {0.f, 0.f, 0.f, 0.f};
        float hp[4]   = {0.f, 0.f, 0.f, 0.f};

        if (t > 0) {
            const int tprev = (dir == 0) ? (teff - 1) : (teff + 1);
            const float* h_prev = y + ((size_t)(dir * TT + tprev) * BB) * HH;

#pragma unroll
            for (int it = 0; it < 16; it++) {
                int idx = tid + 256 * it;
                int kq  = idx & 63;
                int b   = idx >> 6;
                float4 v = *(const float4*)(h_prev + (size_t)(b0 + b) * HH + kq * 4);
                *(float4*)&hs[b * HS_PITCH + kq * 4] = v;
            }
            __syncthreads();

#pragma unroll 4
            for (int k = 0; k < HH; k++) {
                float wr = ws[(0 * 256 + k) * 16 + tn];
                float wz = ws[(1 * 256 + k) * 16 + tn];
                float wn = ws[(2 * 256 + k) * 16 + tn];
#pragma unroll
                for (int i = 0; i < 4; i++) {
                    float h = hs[(bb + i) * HS_PITCH + k];
                    accr[i] += h * wr;
                    accz[i] += h * wz;
                    accn[i] += h * wn;
                }
            }

#pragma unroll
            for (int i = 0; i < 4; i++)
                hp[i] = hs[(bb + i) * HS_PITCH + jg];
        }

#pragma unroll
        for (int i = 0; i < 4; i++) {
            float r = 1.f / (1.f + expf(-(gr[i] + accr[i] + bhr)));
            float z = 1.f / (1.f + expf(-(gz[i] + accz[i] + bhz)));
            float n = tanhf(gn[i] + r * (accn[i] + bhn));
            float o = (1.f - z) * n + z * hp[i];
            y_t[(size_t)(b0 + bb + i) * HH + jg] = o;
        }

        if (t < TT - 1) {
            __syncthreads();
            if (tid == 0) {
                __threadfence();
                atomicAdd(&g_ctrs[grp], 1);
                unsigned target = (unsigned)(t + 1) * 16;
                while (*vc < target) { }
                __threadfence();
            }
            __syncthreads();
        }
    }

    // deadlock-safe per-group counter reset for graph replay
    __syncthreads();
    if (tid == 0) {
        atomicAdd(&g_ctre[grp], 1);
        if ((bid & 15) == 0) {
            volatile unsigned* ve = &g_ctre[grp];
            while (*ve < 16) { }
            *(volatile unsigned*)&g_ctrs[grp] = 0;
            *(volatile unsigned*)&g_ctre[grp] = 0;
            __threadfence();
        }
    }
}

// =================================================================
// Gather: out[b][0:H] = y1_fwd[T-1][b], out[b][H:2H] = y1_bwd[0][b]
// =================================================================
__global__ void gather_kernel(float* __restrict__ out)
{
    int idx = blockIdx.x * blockDim.x + threadIdx.x;
    int b = idx >> 9;
    int j = idx & 511;
    float v;
    if (j < HH)
        v = g_y1[(((size_t)0 * TT + (TT - 1)) * BB + b) * HH + j];
    else
        v = g_y1[(((size_t)1 * TT + 0) * BB + b) * HH + (j - HH)];
    out[idx] = v;
}

// =================================================================
extern "C" void kernel_launch(void* const* d_in, const int* in_sizes, int n_in,
                              void* d_out, int out_size)
{
    const float* x     = (const float*)d_in[0];
    const float* w_ih0 = (const float*)d_in[1];
    const float* w_hh0 = (const float*)d_in[2];
    const float* b_ih0 = (const float*)d_in[3];
    const float* b_hh0 = (const float*)d_in[4];
    const float* w_ih1 = (const float*)d_in[5];
    const float* w_hh1 = (const float*)d_in[6];
    const float* b_ih1 = (const float*)d_in[7];
    const float* b_hh1 = (const float*)d_in[8];
    float* out = (float*)d_out;

    const int layer_smem = (3 * 256 * 16 + 64 * HS_PITCH) * sizeof(float);
    cudaFuncSetAttribute(layer_kernel<0>,
                         cudaFuncAttributeMaxDynamicSharedMemorySize, layer_smem);
    cudaFuncSetAttribute(layer_kernel<1>,
                         cudaFuncAttributeMaxDynamicSharedMemorySize, layer_smem);

    dim3 mma_grid(512, 12, 2);   // m-tiles(65536/128), n-tiles(768/64), dirs

    gi_mma_kernel<DD, 0><<<mma_grid, 256>>>(x, w_ih0, b_ih0);
    layer_kernel<0><<<NBLK, 256, layer_smem>>>(w_hh0, b_hh0);
    gi_mma_kernel<2 * HH, 1><<<mma_grid, 256>>>(nullptr, w_ih1, b_ih1);
    layer_kernel<1><<<NBLK, 256, layer_smem>>>(w_hh1, b_hh1);
    gather_kernel<<<512, 256>>>(out);
}

// round 8
// speedup vs baseline: 3.1970x; 1.3724x over previous
#include <cuda_runtime.h>
#include <math.h>
#include <cstdint>

#define BB 256
#define TT 256
#define DD 64
#define HH 256
#define G3 768   // 3*H
#define NBLK 128

// ---------------- device scratch (allocation-free) ----------------
__device__ float g_gi0[2ull * TT * BB * G3];
__device__ float g_gi1[2ull * TT * BB * G3];
__device__ float g_y0 [2ull * TT * BB * HH];
__device__ float g_y1 [2ull * TT * BB * HH];
__device__ unsigned g_ctrs[8];   // per-group step counters (zero-init)
__device__ unsigned g_ctre[8];   // per-group exit counters (zero-init)

// ================= mma.sync tf32 helpers (sm_80+, family-agnostic) ========
__device__ __forceinline__ uint32_t f2tf32(float f) {
    uint32_t r;
    asm("cvt.rna.tf32.f32 %0, %1;" : "=r"(r) : "f"(f));
    return r;
}
__device__ __forceinline__ void mma1688(float* d, const uint32_t* a, const uint32_t* b) {
    asm volatile(
        "mma.sync.aligned.m16n8k8.row.col.f32.tf32.tf32.f32 "
        "{%0,%1,%2,%3}, {%4,%5,%6,%7}, {%8,%9}, {%0,%1,%2,%3};"
        : "+f"(d[0]), "+f"(d[1]), "+f"(d[2]), "+f"(d[3])
        : "r"(a[0]), "r"(a[1]), "r"(a[2]), "r"(a[3]), "r"(b[0]), "r"(b[1]));
}

// =================================================================
// gi GEMM via mma.sync tf32 (unchanged from R7).
// =================================================================
#define KC 32
#define AP 36

template<int KDIM, int MODE>
__global__ __launch_bounds__(256)
void gi_mma_kernel(const float* __restrict__ x,
                   const float* __restrict__ w_ih,   // [2][G3][KDIM]
                   const float* __restrict__ b_ih)   // [2][G3]
{
    __shared__ uint32_t as[128 * AP];
    __shared__ uint32_t wsm[64 * AP];

    const int tid  = threadIdx.x;
    const int wid  = tid >> 5;
    const int lane = tid & 31;
    const int g    = lane >> 2;
    const int tig  = lane & 3;

    const int bx  = blockIdx.x;
    const int t   = bx >> 1;
    const int b0  = (bx & 1) * 128;
    const int n0  = blockIdx.y * 64;
    const int dir = blockIdx.z;

    const int wm = wid >> 1;
    const int wn = wid & 1;

    const float* wdir = w_ih + (size_t)dir * G3 * KDIM;

    float acc[2][4][4];
#pragma unroll
    for (int mf = 0; mf < 2; mf++)
#pragma unroll
        for (int nf = 0; nf < 4; nf++)
#pragma unroll
            for (int q = 0; q < 4; q++) acc[mf][nf][q] = 0.f;

    for (int c = 0; c < KDIM / KC; c++) {
        const int koff = c * KC;

#pragma unroll
        for (int i = 0; i < 4; i++) {
            int idx = tid + 256 * i;
            int row = idx >> 3;
            int kq  = (idx & 7) * 4;
            float4 v;
            if (MODE == 0) {
                v = *(const float4*)(x + ((size_t)(b0 + row) * TT + t) * DD + koff + kq);
            } else {
                int k = koff + kq;
                if (k < HH)
                    v = *(const float4*)(g_y0 + ((size_t)t * BB + b0 + row) * HH + k);
                else
                    v = *(const float4*)(g_y0 + (size_t)TT * BB * HH +
                                         ((size_t)t * BB + b0 + row) * HH + (k - HH));
            }
            uint32_t* p = &as[row * AP + kq];
            p[0] = f2tf32(v.x); p[1] = f2tf32(v.y);
            p[2] = f2tf32(v.z); p[3] = f2tf32(v.w);
        }
#pragma unroll
        for (int i = 0; i < 2; i++) {
            int idx = tid + 256 * i;
            int row = idx >> 3;
            int kq  = (idx & 7) * 4;
            float4 v = *(const float4*)(wdir + (size_t)(n0 + row) * KDIM + koff + kq);
            uint32_t* p = &wsm[row * AP + kq];
            p[0] = f2tf32(v.x); p[1] = f2tf32(v.y);
            p[2] = f2tf32(v.z); p[3] = f2tf32(v.w);
        }
        __syncthreads();

#pragma unroll
        for (int kk = 0; kk < KC; kk += 8) {
            uint32_t afr[2][4], bfr[4][2];
#pragma unroll
            for (int mf = 0; mf < 2; mf++) {
                int base = wm * 32 + mf * 16;
                afr[mf][0] = as[(base + g)     * AP + kk + tig];
                afr[mf][1] = as[(base + g + 8) * AP + kk + tig];
                afr[mf][2] = as[(base + g)     * AP + kk + tig + 4];
                afr[mf][3] = as[(base + g + 8) * AP + kk + tig + 4];
            }
#pragma unroll
            for (int nf = 0; nf < 4; nf++) {
                int nb = wn * 32 + nf * 8;
                bfr[nf][0] = wsm[(nb + g) * AP + kk + tig];
                bfr[nf][1] = wsm[(nb + g) * AP + kk + tig + 4];
            }
#pragma unroll
            for (int mf = 0; mf < 2; mf++)
#pragma unroll
                for (int nf = 0; nf < 4; nf++)
                    mma1688(acc[mf][nf], afr[mf], bfr[nf]);
        }
        __syncthreads();
    }

    float* gout = (MODE == 0) ? g_gi0 : g_gi1;
    const float* bias = b_ih + dir * G3;

#pragma unroll
    for (int mf = 0; mf < 2; mf++) {
#pragma unroll
        for (int rs = 0; rs < 2; rs++) {
            int mloc = wm * 32 + mf * 16 + g + rs * 8;
            int b = b0 + mloc;
            float* orow = gout + (((size_t)dir * TT + t) * BB + b) * G3 + n0;
#pragma unroll
            for (int nf = 0; nf < 4; nf++) {
                int col = wn * 32 + nf * 8 + 2 * tig;
                float2 o;
                o.x = acc[mf][nf][rs * 2 + 0] + bias[n0 + col];
                o.y = acc[mf][nf][rs * 2 + 1] + bias[n0 + col + 1];
                *(float2*)(orow + col) = o;
            }
        }
    }
}

// =================================================================
// Persistent per-layer recurrence kernel with tf32 mma.sync.
// Grid = 128 blocks (dir | b-tile(64) | j-tile(16)), 256 thr = 8 warps.
// Warp = (wm: 16 b-rows) x (wn: 8 j x 3 gates).
// Weights pre-packed as b-fragments in smem (once); h staged per step
// as tf32 hi/lo split (2 MMAs -> A effectively fp32).
// smem: wsf 48KB + hs_hi 65KB + hs_lo 65KB = 178KB.
// =================================================================
#define HSP 260                     // hs pitch (floats): conflict-free a-frags
#define WSF_BYTES (3 * 2 * 32 * 32 * 8)         // 49152
#define HS_BYTES  (64 * HSP * 4)                 // 66560
#define LAYER_SMEM (WSF_BYTES + 2 * HS_BYTES)    // 182272

template<int LAYER>
__global__ __launch_bounds__(256)
void layer_kernel(const float* __restrict__ w_hh,   // [2][G3][H]
                  const float* __restrict__ b_hh)   // [2][G3]
{
    extern __shared__ char smraw[];
    uint2*    wsf   = (uint2*)smraw;
    uint32_t* hs_hi = (uint32_t*)(smraw + WSF_BYTES);
    uint32_t* hs_lo = (uint32_t*)(smraw + WSF_BYTES + HS_BYTES);

    const int bid = blockIdx.x;
    const int dir = bid >> 6;
    const int rr  = bid & 63;
    const int j0  = (rr & 15) * 16;
    const int b0  = (rr >> 4) * 64;
    const int grp = bid >> 4;

    const int tid  = threadIdx.x;
    const int wid  = tid >> 5;
    const int lane = tid & 31;
    const int g    = lane >> 2;
    const int tig  = lane & 3;
    const int wm   = wid >> 1;      // 0..3: m sub-tile (16 rows)
    const int wn   = wid & 1;       // 0..1: j half (8 cols)

    const float* gi = LAYER ? g_gi1 : g_gi0;
    float*       y  = LAYER ? g_y1  : g_y0;
    const float* w  = w_hh + (size_t)dir * G3 * HH;
    const float* bh = b_hh + dir * G3;

    // ---- pack weight fragments once: wsf[g3][wn][kk][lane] = (W[k0], W[k0+4]) ----
    for (int e = tid; e < 3 * 2 * 32 * 32; e += 256) {
        int el = e & 31;
        int kk = (e >> 5) & 31;
        int ww = (e >> 10) & 1;
        int g3 = e >> 11;
        int j  = j0 + ww * 8 + (el >> 2);
        int k0 = kk * 8 + (el & 3);
        const float* wr = w + (size_t)(g3 * HH + j) * HH;
        uint2 bv;
        bv.x = f2tf32(wr[k0]);
        bv.y = f2tf32(wr[k0 + 4]);
        wsf[e] = bv;
    }

    // per-thread j columns (same for both row halves)
    const int jj = wn * 8 + 2 * tig;      // local j in [0,16)
    const int jglob = j0 + jj;            // global hidden index
    float2 bhr = *(const float2*)&bh[jglob];
    float2 bhz = *(const float2*)&bh[HH + jglob];
    float2 bhn = *(const float2*)&bh[2 * HH + jglob];

    __syncthreads();

    volatile unsigned* vc = &g_ctrs[grp];
    const uint2* wsf_w = wsf + (size_t)wn * 1024;   // [g3][kk][lane]
    const int r0 = wm * 16;                          // warp's local row base

    for (int t = 0; t < TT; t++) {
        const int teff = (dir == 0) ? t : (TT - 1 - t);
        const float* gi_t = gi + ((size_t)(dir * TT + teff) * BB) * G3;
        float*       y_t  = y  + ((size_t)(dir * TT + teff) * BB) * HH;

        float acc[3][4];
#pragma unroll
        for (int g3 = 0; g3 < 3; g3++)
#pragma unroll
            for (int q = 0; q < 4; q++) acc[g3][q] = 0.f;

        if (t > 0) {
            const int tprev = (dir == 0) ? (teff - 1) : (teff + 1);
            const float* h_prev = y + ((size_t)(dir * TT + tprev) * BB) * HH;

            // ---- stage h slice as tf32 hi/lo: hs[b][k] ----
#pragma unroll
            for (int it = 0; it < 16; it++) {
                int idx = tid + 256 * it;      // 0..4095
                int kq  = idx & 63;
                int b   = idx >> 6;
                float4 v = *(const float4*)(h_prev + (size_t)(b0 + b) * HH + kq * 4);
                uint4 hi, lo;
                hi.x = f2tf32(v.x); lo.x = f2tf32(v.x - __uint_as_float(hi.x));
                hi.y = f2tf32(v.y); lo.y = f2tf32(v.y - __uint_as_float(hi.y));
                hi.z = f2tf32(v.z); lo.z = f2tf32(v.z - __uint_as_float(hi.z));
                hi.w = f2tf32(v.w); lo.w = f2tf32(v.w - __uint_as_float(hi.w));
                *(uint4*)&hs_hi[b * HSP + kq * 4] = hi;
                *(uint4*)&hs_lo[b * HSP + kq * 4] = lo;
            }
            __syncthreads();

            // ---- tensor k-loop: 32 x k8, 2 MMAs (hi+lo) x 3 gates ----
#pragma unroll 4
            for (int kk = 0; kk < 32; kk++) {
                int ko = kk * 8;
                uint32_t ahi[4], alo[4];
                ahi[0] = hs_hi[(r0 + g)     * HSP + ko + tig];
                ahi[1] = hs_hi[(r0 + g + 8) * HSP + ko + tig];
                ahi[2] = hs_hi[(r0 + g)     * HSP + ko + tig + 4];
                ahi[3] = hs_hi[(r0 + g + 8) * HSP + ko + tig + 4];
                alo[0] = hs_lo[(r0 + g)     * HSP + ko + tig];
                alo[1] = hs_lo[(r0 + g + 8) * HSP + ko + tig];
                alo[2] = hs_lo[(r0 + g)     * HSP + ko + tig + 4];
                alo[3] = hs_lo[(r0 + g + 8) * HSP + ko + tig + 4];
#pragma unroll
                for (int g3 = 0; g3 < 3; g3++) {
                    uint2 bv = wsf_w[g3 * 2048 + kk * 32 + lane];
                    uint32_t bf[2] = {bv.x, bv.y};
                    mma1688(acc[g3], ahi, bf);
                    mma1688(acc[g3], alo, bf);
                }
            }
        }

        // ---- gate math + store: 2 row-halves x 2 j cols per thread ----
#pragma unroll
        for (int rs = 0; rs < 2; rs++) {
            const int rl = r0 + g + rs * 8;          // local row
            const int b  = b0 + rl;                  // global batch row
            const float* girow = gi_t + (size_t)b * G3;
            float2 gir = *(const float2*)&girow[jglob];
            float2 giz = *(const float2*)&girow[HH + jglob];
            float2 gin = *(const float2*)&girow[2 * HH + jglob];

            float hp0 = 0.f, hp1 = 0.f;
            if (t > 0) {
                hp0 = __uint_as_float(hs_hi[rl * HSP + jglob]) +
                      __uint_as_float(hs_lo[rl * HSP + jglob]);
                hp1 = __uint_as_float(hs_hi[rl * HSP + jglob + 1]) +
                      __uint_as_float(hs_lo[rl * HSP + jglob + 1]);
            }

            float ar0 = acc[0][rs * 2 + 0] + bhr.x;
            float ar1 = acc[0][rs * 2 + 1] + bhr.y;
            float az0 = acc[1][rs * 2 + 0] + bhz.x;
            float az1 = acc[1][rs * 2 + 1] + bhz.y;
            float an0 = acc[2][rs * 2 + 0] + bhn.x;
            float an1 = acc[2][rs * 2 + 1] + bhn.y;

            float rv0 = 1.f / (1.f + expf(-(gir.x + ar0)));
            float rv1 = 1.f / (1.f + expf(-(gir.y + ar1)));
            float zv0 = 1.f / (1.f + expf(-(giz.x + az0)));
            float zv1 = 1.f / (1.f + expf(-(giz.y + az1)));
            float nv0 = tanhf(gin.x + rv0 * an0);
            float nv1 = tanhf(gin.y + rv1 * an1);

            float2 o;
            o.x = (1.f - zv0) * nv0 + zv0 * hp0;
            o.y = (1.f - zv1) * nv1 + zv1 * hp1;
            *(float2*)(y_t + (size_t)b * HH + jglob) = o;
        }

        // ---- group barrier (16 blocks sharing (dir, b-tile)) ----
        if (t < TT - 1) {
            __syncthreads();
            if (tid == 0) {
                __threadfence();
                atomicAdd(&g_ctrs[grp], 1);
                unsigned target = (unsigned)(t + 1) * 16;
                while (*vc < target) { }
                __threadfence();
            }
            __syncthreads();
        }
    }

    // deadlock-safe per-group counter reset for graph replay
    __syncthreads();
    if (tid == 0) {
        atomicAdd(&g_ctre[grp], 1);
        if ((bid & 15) == 0) {
            volatile unsigned* ve = &g_ctre[grp];
            while (*ve < 16) { }
            *(volatile unsigned*)&g_ctrs[grp] = 0;
            *(volatile unsigned*)&g_ctre[grp] = 0;
            __threadfence();
        }
    }
}

// =================================================================
// Gather: out[b][0:H] = y1_fwd[T-1][b], out[b][H:2H] = y1_bwd[0][b]
// =================================================================
__global__ void gather_kernel(float* __restrict__ out)
{
    int idx = blockIdx.x * blockDim.x + threadIdx.x;
    int b = idx >> 9;
    int j = idx & 511;
    float v;
    if (j < HH)
        v = g_y1[(((size_t)0 * TT + (TT - 1)) * BB + b) * HH + j];
    else
        v = g_y1[(((size_t)1 * TT + 0) * BB + b) * HH + (j - HH)];
    out[idx] = v;
}

// =================================================================
extern "C" void kernel_launch(void* const* d_in, const int* in_sizes, int n_in,
                              void* d_out, int out_size)
{
    const float* x     = (const float*)d_in[0];
    const float* w_ih0 = (const float*)d_in[1];
    const float* w_hh0 = (const float*)d_in[2];
    const float* b_ih0 = (const float*)d_in[3];
    const float* b_hh0 = (const float*)d_in[4];
    const float* w_ih1 = (const float*)d_in[5];
    const float* w_hh1 = (const float*)d_in[6];
    const float* b_ih1 = (const float*)d_in[7];
    const float* b_hh1 = (const float*)d_in[8];
    float* out = (float*)d_out;

    cudaFuncSetAttribute(layer_kernel<0>,
                         cudaFuncAttributeMaxDynamicSharedMemorySize, LAYER_SMEM);
    cudaFuncSetAttribute(layer_kernel<1>,
                         cudaFuncAttributeMaxDynamicSharedMemorySize, LAYER_SMEM);

    dim3 mma_grid(512, 12, 2);   // m-tiles(65536/128), n-tiles(768/64), dirs

    gi_mma_kernel<DD, 0><<<mma_grid, 256>>>(x, w_ih0, b_ih0);
    layer_kernel<0><<<NBLK, 256, LAYER_SMEM>>>(w_hh0, b_hh0);
    gi_mma_kernel<2 * HH, 1><<<mma_grid, 256>>>(nullptr, w_ih1, b_ih1);
    layer_kernel<1><<<NBLK, 256, LAYER_SMEM>>>(w_hh1, b_hh1);
    gather_kernel<<<512, 256>>>(out);
}